// round 7
// baseline (speedup 1.0000x reference)
#include <cuda_runtime.h>
#include <cuda_bf16.h>

// FINAL FAMILY. The reference network mathematically collapses: the GNN
// "layernorm" is over a feature axis of size 1, so (y-mean)/sqrt(var+eps)==0
// exactly and h == ln_bias[l] after each propagation layer, independent of
// everything upstream (hash grids, SIREN trunk, member heads, 2M graph edges).
// Output = softplus(ln_bias[1,0]) * sigmoid((1 - psi_n) * 50), elementwise.
//
// Measured saturation (R1-R6): kernel time invariant ~4.1-4.4us across all
// body/grid variants (every ncu pipe ~0%, DRAM 0.8%) — pure launch-latency
// floor. Bench responds only to warp layout at retire, flat at ~4.5-4.6us for
// <=4 warps/SM. R7 probes the one untested layout: 1 warp/CTA (512x32) — CTA
// retires with its single warp, no intra-CTA exit join. Expected neutral.

__global__ __launch_bounds__(32, 32)
void collapsed_forward_kernel(const float* __restrict__ psi_n,
                              const float* __restrict__ ln_bias,
                              float* __restrict__ out) {
    int i = blockIdx.x * 32 + threadIdx.x;   // exactly 16384 threads = n/4

    // Issue both loads immediately so their DRAM latencies overlap.
    float4 p = reinterpret_cast<const float4*>(psi_n)[i];
    float b = __ldg(&ln_bias[1]);

    float refined = __logf(1.0f + __expf(b));   // softplus(ln_bias[1])

    // refined * sigmoid((1-p)*50); sigmoid arg negated: (p-1)*50 = fma(p,50,-50)
    float4 r;
    r.x = __fdividef(refined, 1.0f + __expf(fmaf(p.x, 50.0f, -50.0f)));
    r.y = __fdividef(refined, 1.0f + __expf(fmaf(p.y, 50.0f, -50.0f)));
    r.z = __fdividef(refined, 1.0f + __expf(fmaf(p.z, 50.0f, -50.0f)));
    r.w = __fdividef(refined, 1.0f + __expf(fmaf(p.w, 50.0f, -50.0f)));
    reinterpret_cast<float4*>(out)[i] = r;
}

extern "C" void kernel_launch(void* const* d_in, const int* in_sizes, int n_in,
                              void* d_out, int out_size) {
    const float* psi_n   = (const float*)d_in[2];
    const float* ln_bias = (const float*)d_in[25];
    float* out = (float*)d_out;

    int n4 = out_size / 4;          // 16384
    int blocks = n4 / 32;           // 512 CTAs x 32 threads (1 warp/CTA)
    collapsed_forward_kernel<<<blocks, 32>>>(psi_n, ln_bias, out);
}